// round 6
// baseline (speedup 1.0000x reference)
#include <cuda_runtime.h>

#define H 512
#define W 512
#define CH 3
#define NS 48               // 16 batches * 3 channels
#define SYS (H*W)
#define NTOT (NS*SYS)
#define RTOT (NS*H)         // 24576 rows
#define WCN (511*512)
#define WRN (512*511)
#define MAXIT 100
#define EPS_F 158.32966f    // (1e-6 * 16*3*512*512)^2
#define TPB 512
#define NGRP (TPB/128)      // 4 sweep groups per block
#define PFD 3               // prefetch distance (rows)

__device__ float g_r[NTOT];
__device__ float g_pbuf[2][NTOT];
__device__ float g_pAp[3][NS*8];
__device__ float g_rr[3][NS*8];
__device__ unsigned int g_bar_arrive;
__device__ volatile unsigned int g_bar_phase;

__device__ __forceinline__ float4 ld4(const float* p) { return *reinterpret_cast<const float4*>(p); }
__device__ __forceinline__ void st4(float* p, float4 v) { *reinterpret_cast<float4*>(p) = v; }
__device__ __forceinline__ void pf2(const void* p) {
    asm volatile("prefetch.global.L2 [%0];" :: "l"(p));
}

__device__ __forceinline__ float nan0(float v) {
    if (isnan(v)) return 0.0f;
    if (isinf(v)) return v > 0.f ? 3.402823466e38f : -3.402823466e38f;
    return v;
}

__device__ __forceinline__ void grid_barrier(int G, unsigned int &gen) {
    __syncthreads();
    if (threadIdx.x == 0) {
        __threadfence();
        unsigned int t = atomicAdd(&g_bar_arrive, 1u);
        if (t == (unsigned int)(G - 1)) {
            g_bar_arrive = 0;
            __threadfence();
            g_bar_phase = gen + 1u;
        } else {
            while (g_bar_phase == gen) { __nanosleep(64); }
        }
        gen++;
        __threadfence();
    }
    __syncthreads();
}

// Register-rolling sweep over rows [i0,i1) of one system.
// Source field z: zsrc (COMBINE: z = zsrc + coef * pb, formed on load).
// Stencil y = (I + L_w) z with implicit diagonal: y = z + sum_e w_e (z - z_nbr).
// PASS 0 (setup): o1 <- z - y (=r), o2 <- z (=x), acc += |r|^2
// PASS 1:         o1 <- z (=p),                   acc += z . y  (p.Ap)
// PASS 2:         o1 -= coef*y (r), o2 += coef*z (x), acc += |r|^2
template<int PASS, bool COMBINE>
__device__ __forceinline__ void sweep_seg(
    const float* __restrict__ zsrc, const float* __restrict__ pb, float coef,
    const float* __restrict__ wcb, const float* __restrict__ wrb,
    float* __restrict__ o1, float* __restrict__ o2,
    int i0, int i1, int j0, int lane, float &acc)
{
    float4 zu = make_float4(0.f,0.f,0.f,0.f), zc, zd = make_float4(0.f,0.f,0.f,0.f);
    float4 wcu = make_float4(0.f,0.f,0.f,0.f), wcd = wcu;

    if (i0 > 0) {
        int e = (i0 - 1) * W + j0;
        zu = ld4(zsrc + e);
        if (COMBINE) {
            float4 q = ld4(pb + e);
            zu.x = fmaf(coef, q.x, zu.x); zu.y = fmaf(coef, q.y, zu.y);
            zu.z = fmaf(coef, q.z, zu.z); zu.w = fmaf(coef, q.w, zu.w);
        }
        wcu = ld4(wcb + (i0 - 1) * W + j0);
    }
    {
        int e = i0 * W + j0;
        zc = ld4(zsrc + e);
        if (COMBINE) {
            float4 q = ld4(pb + e);
            zc.x = fmaf(coef, q.x, zc.x); zc.y = fmaf(coef, q.y, zc.y);
            zc.z = fmaf(coef, q.z, zc.z); zc.w = fmaf(coef, q.w, zc.w);
        }
    }

    int gi = i0 * W + j0;
    for (int i = i0; i < i1; ++i, gi += W) {
        const bool dn = (i < H - 1);

        // L2 prefetch PFD rows ahead (fire-and-forget, no regs/scoreboard)
        if (i + PFD < H) {
            int gp = gi + PFD * W;
            pf2(zsrc + gp);
            if (COMBINE) pf2(pb + gp);
            if (i + PFD < H - 1) pf2(wcb + (i + PFD) * W + j0);
            pf2(wrb + (i + PFD) * 511 + j0);
            if (PASS == 2) { pf2(o1 + gp); pf2(o2 + gp); }
        }

        if (dn) {
            zd = ld4(zsrc + gi + W);
            if (COMBINE) {
                float4 q = ld4(pb + gi + W);
                zd.x = fmaf(coef, q.x, zd.x); zd.y = fmaf(coef, q.y, zd.y);
                zd.z = fmaf(coef, q.z, zd.z); zd.w = fmaf(coef, q.w, zd.w);
            }
            wcd = ld4(wcb + i * W + j0);
        }

        const float* wrow = wrb + i * 511;
        float wA = wrow[j0], wB = wrow[j0 + 1], wC = wrow[j0 + 2];
        float wD = (j0 < 508) ? wrow[j0 + 3] : 0.f;
        float wl = __shfl_up_sync(0xffffffffu, wD, 1);
        float xl = __shfl_up_sync(0xffffffffu, zc.w, 1);
        float xr = __shfl_down_sync(0xffffffffu, zc.x, 1);
        if (lane == 0 && j0 > 0) {          // warp-edge fixups (L1 hits)
            xl = zsrc[gi - 1];
            if (COMBINE) xl = fmaf(coef, pb[gi - 1], xl);
            wl = wrow[j0 - 1];
        }
        if (lane == 31 && j0 + 4 < W) {
            xr = zsrc[gi + 4];
            if (COMBINE) xr = fmaf(coef, pb[gi + 4], xr);
        }

        float y0 = zc.x, y1 = zc.y, y2 = zc.z, y3 = zc.w;
        if (i > 0) {
            y0 += wcu.x * (zc.x - zu.x); y1 += wcu.y * (zc.y - zu.y);
            y2 += wcu.z * (zc.z - zu.z); y3 += wcu.w * (zc.w - zu.w);
        }
        if (dn) {
            y0 += wcd.x * (zc.x - zd.x); y1 += wcd.y * (zc.y - zd.y);
            y2 += wcd.z * (zc.z - zd.z); y3 += wcd.w * (zc.w - zd.w);
        }
        y0 += wA * (zc.x - zc.y);
        y1 += wA * (zc.y - zc.x) + wB * (zc.y - zc.z);
        y2 += wB * (zc.z - zc.y) + wC * (zc.z - zc.w);
        y3 += wC * (zc.w - zc.z);
        if (j0 > 0)      y0 += wl * (zc.x - xl);
        if (j0 + 4 < W)  y3 += wD * (zc.w - xr);

        if (PASS == 0) {
            float4 rn = make_float4(zc.x - y0, zc.y - y1, zc.z - y2, zc.w - y3);
            st4(o1 + gi, rn);
            st4(o2 + gi, zc);
            acc += rn.x * rn.x + rn.y * rn.y + rn.z * rn.z + rn.w * rn.w;
        } else if (PASS == 1) {
            st4(o1 + gi, zc);
            acc += zc.x * y0 + zc.y * y1 + zc.z * y2 + zc.w * y3;
        } else {
            float4 rv = ld4(o1 + gi);
            float4 xv = ld4(o2 + gi);
            rv.x -= coef * y0; rv.y -= coef * y1;
            rv.z -= coef * y2; rv.w -= coef * y3;
            xv.x = fmaf(coef, zc.x, xv.x); xv.y = fmaf(coef, zc.y, xv.y);
            xv.z = fmaf(coef, zc.z, xv.z); xv.w = fmaf(coef, zc.w, xv.w);
            st4(o1 + gi, rv);
            st4(o2 + gi, xv);
            acc += rv.x * rv.x + rv.y * rv.y + rv.z * rv.z + rv.w * rv.w;
        }
        zu = zc; zc = zd; wcu = wcd;
    }
}

// Block covers contiguous rows spanning at most 2 systems (s0, s0+1).
__device__ __forceinline__ void reduce2_atomic(float a0, float a1, int s0, int r1, float* dst)
{
    __shared__ float sm[2][TPB / 32];
    #pragma unroll
    for (int o = 16; o; o >>= 1) {
        a0 += __shfl_down_sync(0xffffffffu, a0, o);
        a1 += __shfl_down_sync(0xffffffffu, a1, o);
    }
    int wid = threadIdx.x >> 5, lid = threadIdx.x & 31;
    if (lid == 0) { sm[0][wid] = a0; sm[1][wid] = a1; }
    __syncthreads();
    if (threadIdx.x < 32) {
        a0 = (lid < TPB / 32) ? sm[0][lid] : 0.f;
        a1 = (lid < TPB / 32) ? sm[1][lid] : 0.f;
        #pragma unroll
        for (int o = 16; o; o >>= 1) {
            a0 += __shfl_down_sync(0xffffffffu, a0, o);
            a1 += __shfl_down_sync(0xffffffffu, a1, o);
        }
        if (lid == 0) {
            atomicAdd(dst + s0 * 8, a0);
            if (s0 + 1 < NS && (s0 + 1) * H < r1) atomicAdd(dst + (s0 + 1) * 8, a1);
        }
    }
    __syncthreads();
}

// Iterate system-aligned segments of [q0,q1): calls f(s, i0, i1).
template<typename F>
__device__ __forceinline__ void for_segs(int q0, int q1, F f)
{
    int a = q0;
    while (a < q1) {
        int s = a >> 9;
        int send = q1 < ((s + 1) << 9) ? q1 : ((s + 1) << 9);
        f(s, a & 511, (a & 511) + (send - a));
        a = send;
    }
}

extern "C" __global__ void __launch_bounds__(TPB, 2)
cg_persistent(const float* __restrict__ Bin, const float* __restrict__ wc,
              const float* __restrict__ wr, float* __restrict__ x, int G)
{
    unsigned int gen = g_bar_phase;   // survives graph replays
    const int bi = blockIdx.x;
    const int r0 = (int)(((long long)bi * RTOT) / G);
    const int r1 = (int)(((long long)(bi + 1) * RTOT) / G);
    const int s0 = r0 >> 9;
    const int grp = threadIdx.x >> 7;
    const int j0 = (threadIdx.x & 127) << 2;
    const int lane = threadIdx.x & 31;
    const int q0 = r0 + (int)(((long long)(r1 - r0) * grp) / NGRP);
    const int q1 = r0 + (int)(((long long)(r1 - r0) * (grp + 1)) / NGRP);

    if (bi == 0) {
        for (int t = threadIdx.x; t < 3 * NS * 8; t += TPB) {
            (&g_pAp[0][0])[t] = 0.f;
            (&g_rr[0][0])[t] = 0.f;
        }
    }
    grid_barrier(G, gen);

    // Setup: x = B; r = B - A*B; rr0 -> slot 0
    {
        float a0 = 0.f, a1 = 0.f;
        for_segs(q0, q1, [&](int s, int i0, int i1) {
            int b = s / CH;
            float acc = 0.f;
            sweep_seg<0, false>(Bin + s * SYS, (const float*)0, 0.f,
                                wc + b * WCN, wr + b * WRN,
                                g_r + s * SYS, x + s * SYS, i0, i1, j0, lane, acc);
            if (s == s0) a0 += acc; else a1 += acc;
        });
        reduce2_atomic(a0, a1, s0, r1, g_rr[0]);
    }
    grid_barrier(G, gen);

    for (int it = 0; it < MAXIT; ++it) {
        const int cur = it % 3, prv = (it + 2) % 3, nxt = (it + 1) % 3;
        float* __restrict__ pnew = g_pbuf[it & 1];
        const float* __restrict__ pold = g_pbuf[(it + 1) & 1];

        // Pass 1: p = r + beta*p_old formed on load; store p; pAp dot (no Ap store)
        {
            float a0 = 0.f, a1 = 0.f;
            for_segs(q0, q1, [&](int s, int i0, int i1) {
                int b = s / CH;
                float acc = 0.f;
                if (it == 0) {
                    sweep_seg<1, false>(g_r + s * SYS, (const float*)0, 0.f,
                                        wc + b * WCN, wr + b * WRN,
                                        pnew + s * SYS, (float*)0, i0, i1, j0, lane, acc);
                } else {
                    float beta = nan0(g_rr[cur][s * 8] / g_rr[prv][s * 8]);
                    sweep_seg<1, true>(g_r + s * SYS, pold + s * SYS, beta,
                                       wc + b * WCN, wr + b * WRN,
                                       pnew + s * SYS, (float*)0, i0, i1, j0, lane, acc);
                }
                if (s == s0) a0 += acc; else a1 += acc;
            });
            reduce2_atomic(a0, a1, s0, r1, g_pAp[cur]);
            if (bi == 0) {
                for (int t = threadIdx.x; t < NS * 8; t += TPB) g_rr[nxt][t] = 0.f;
            }
        }
        grid_barrier(G, gen);

        // Pass 2: recompute Ap from p; r -= a*Ap; x += a*p; rr dot
        {
            float a0 = 0.f, a1 = 0.f;
            for_segs(q0, q1, [&](int s, int i0, int i1) {
                int b = s / CH;
                float alpha = nan0(g_rr[cur][s * 8] / g_pAp[cur][s * 8]);
                float acc = 0.f;
                sweep_seg<2, false>(pnew + s * SYS, (const float*)0, alpha,
                                    wc + b * WCN, wr + b * WRN,
                                    g_r + s * SYS, x + s * SYS, i0, i1, j0, lane, acc);
                if (s == s0) a0 += acc; else a1 += acc;
            });
            reduce2_atomic(a0, a1, s0, r1, g_rr[nxt]);
            if (bi == 0) {
                for (int t = threadIdx.x; t < NS * 8; t += TPB) g_pAp[nxt][t] = 0.f;
            }
        }
        grid_barrier(G, gen);

        // Convergence (uniform across blocks)
        __shared__ int s_done;
        if (threadIdx.x == 0) {
            float tot = 0.f;
            for (int s = 0; s < NS; ++s) tot += g_rr[nxt][s * 8];
            s_done = (tot < EPS_F) ? 1 : 0;
        }
        __syncthreads();
        if (s_done) break;
    }
}

extern "C" void kernel_launch(void* const* d_in, const int* in_sizes, int n_in,
                              void* d_out, int out_size)
{
    static int G = 0;
    if (G == 0) {
        int dev = 0;
        cudaGetDevice(&dev);
        int sms = 0;
        cudaDeviceGetAttribute(&sms, cudaDevAttrMultiProcessorCount, dev);
        int occ = 0;
        cudaOccupancyMaxActiveBlocksPerMultiprocessor(&occ, cg_persistent, TPB, 0);
        if (occ < 1) occ = 1;
        G = sms * occ;
        if (G > RTOT) G = RTOT;
    }
    cg_persistent<<<G, TPB>>>((const float*)d_in[0], (const float*)d_in[1],
                              (const float*)d_in[2], (float*)d_out, G);
}

// round 7
// speedup vs baseline: 1.1015x; 1.1015x over previous
#include <cuda_runtime.h>

#define H 512
#define W 512
#define CH 3
#define NS 48               // 16 batches * 3 channels
#define SYS (H*W)
#define NTOT (NS*SYS)
#define RTOT (NS*H)         // 24576 rows
#define WCN (511*512)
#define WRN (512*511)
#define MAXIT 100
#define EPS_F 158.32966f    // (1e-6 * 16*3*512*512)^2
#define TPB 512
#define NGRP (TPB/128)      // 4 sweep groups per block

__device__ float g_r[NTOT];
__device__ float g_pbuf[2][NTOT];
__device__ float g_pAp[3][NS*8];
__device__ float g_rr[3][NS*8];
__device__ unsigned int g_bar_arrive;
__device__ volatile unsigned int g_bar_phase;

__device__ __forceinline__ float4 ld4(const float* p) { return *reinterpret_cast<const float4*>(p); }
__device__ __forceinline__ void st4(float* p, float4 v) { *reinterpret_cast<float4*>(p) = v; }

__device__ __forceinline__ float nan0(float v) {
    if (isnan(v)) return 0.0f;
    if (isinf(v)) return v > 0.f ? 3.402823466e38f : -3.402823466e38f;
    return v;
}

__device__ __forceinline__ void grid_barrier(int G, unsigned int &gen) {
    __syncthreads();
    if (threadIdx.x == 0) {
        __threadfence();
        unsigned int t = atomicAdd(&g_bar_arrive, 1u);
        if (t == (unsigned int)(G - 1)) {
            g_bar_arrive = 0;
            __threadfence();
            g_bar_phase = gen + 1u;
        } else {
            while (g_bar_phase == gen) { __nanosleep(64); }
        }
        gen++;
        __threadfence();
    }
    __syncthreads();
}

// Register-rolling sweep over rows [i0,i1) of one system.
// z rolls in registers; column weights are RE-LOADED each row (up-weight row
// was last iteration's down-weight row -> L1 hit) to save registers.
// PASS 0 (setup): o1 <- z - y (=r), o2 <- z (=x), acc += |r|^2
// PASS 1:         o1 <- z (=p),                   acc += z . y  (p.Ap)
// PASS 2:         o1 -= coef*y (r), o2 += coef*z (x), acc += |r|^2
template<int PASS, bool COMBINE>
__device__ __forceinline__ void sweep_seg(
    const float* __restrict__ zsrc, const float* __restrict__ pb, float coef,
    const float* __restrict__ wcb, const float* __restrict__ wrb,
    float* __restrict__ o1, float* __restrict__ o2,
    int i0, int i1, int j0, int lane, float &acc)
{
    float4 zu = make_float4(0.f,0.f,0.f,0.f), zc, zd = make_float4(0.f,0.f,0.f,0.f);

    if (i0 > 0) {
        int e = (i0 - 1) * W + j0;
        zu = ld4(zsrc + e);
        if (COMBINE) {
            float4 q = ld4(pb + e);
            zu.x = fmaf(coef, q.x, zu.x); zu.y = fmaf(coef, q.y, zu.y);
            zu.z = fmaf(coef, q.z, zu.z); zu.w = fmaf(coef, q.w, zu.w);
        }
    }
    {
        int e = i0 * W + j0;
        zc = ld4(zsrc + e);
        if (COMBINE) {
            float4 q = ld4(pb + e);
            zc.x = fmaf(coef, q.x, zc.x); zc.y = fmaf(coef, q.y, zc.y);
            zc.z = fmaf(coef, q.z, zc.z); zc.w = fmaf(coef, q.w, zc.w);
        }
    }

    int gi = i0 * W + j0;
    for (int i = i0; i < i1; ++i, gi += W) {
        const bool dn = (i < H - 1);
        if (dn) {
            zd = ld4(zsrc + gi + W);
            if (COMBINE) {
                float4 q = ld4(pb + gi + W);
                zd.x = fmaf(coef, q.x, zd.x); zd.y = fmaf(coef, q.y, zd.y);
                zd.z = fmaf(coef, q.z, zd.z); zd.w = fmaf(coef, q.w, zd.w);
            }
        }

        const float* wrow = wrb + i * 511;
        float wA = wrow[j0], wB = wrow[j0 + 1], wC = wrow[j0 + 2];
        float wD = (j0 < 508) ? wrow[j0 + 3] : 0.f;
        float wl = __shfl_up_sync(0xffffffffu, wD, 1);
        float xl = __shfl_up_sync(0xffffffffu, zc.w, 1);
        float xr = __shfl_down_sync(0xffffffffu, zc.x, 1);
        if (lane == 0 && j0 > 0) {          // warp-edge fixups (L1 hits)
            xl = zsrc[gi - 1];
            if (COMBINE) xl = fmaf(coef, pb[gi - 1], xl);
            wl = wrow[j0 - 1];
        }
        if (lane == 31 && j0 + 4 < W) {
            xr = zsrc[gi + 4];
            if (COMBINE) xr = fmaf(coef, pb[gi + 4], xr);
        }

        float y0 = zc.x, y1 = zc.y, y2 = zc.z, y3 = zc.w;
        if (i > 0) {                         // up weights: re-load (L1 hit)
            float4 wu = ld4(wcb + (i - 1) * W + j0);
            y0 += wu.x * (zc.x - zu.x); y1 += wu.y * (zc.y - zu.y);
            y2 += wu.z * (zc.z - zu.z); y3 += wu.w * (zc.w - zu.w);
        }
        if (dn) {
            float4 wd = ld4(wcb + i * W + j0);
            y0 += wd.x * (zc.x - zd.x); y1 += wd.y * (zc.y - zd.y);
            y2 += wd.z * (zc.z - zd.z); y3 += wd.w * (zc.w - zd.w);
        }
        y0 += wA * (zc.x - zc.y);
        y1 += wA * (zc.y - zc.x) + wB * (zc.y - zc.z);
        y2 += wB * (zc.z - zc.y) + wC * (zc.z - zc.w);
        y3 += wC * (zc.w - zc.z);
        if (j0 > 0)      y0 += wl * (zc.x - xl);
        if (j0 + 4 < W)  y3 += wD * (zc.w - xr);

        if (PASS == 0) {
            float4 rn = make_float4(zc.x - y0, zc.y - y1, zc.z - y2, zc.w - y3);
            st4(o1 + gi, rn);
            st4(o2 + gi, zc);
            acc += rn.x * rn.x + rn.y * rn.y + rn.z * rn.z + rn.w * rn.w;
        } else if (PASS == 1) {
            st4(o1 + gi, zc);
            acc += zc.x * y0 + zc.y * y1 + zc.z * y2 + zc.w * y3;
        } else {
            float4 rv = ld4(o1 + gi);
            float4 xv = ld4(o2 + gi);
            rv.x -= coef * y0; rv.y -= coef * y1;
            rv.z -= coef * y2; rv.w -= coef * y3;
            xv.x = fmaf(coef, zc.x, xv.x); xv.y = fmaf(coef, zc.y, xv.y);
            xv.z = fmaf(coef, zc.z, xv.z); xv.w = fmaf(coef, zc.w, xv.w);
            st4(o1 + gi, rv);
            st4(o2 + gi, xv);
            acc += rv.x * rv.x + rv.y * rv.y + rv.z * rv.z + rv.w * rv.w;
        }
        zu = zc; zc = zd;
    }
}

// Block covers contiguous rows spanning at most 2 systems (s0, s0+1).
__device__ __forceinline__ void reduce2_atomic(float a0, float a1, int s0, int r1, float* dst)
{
    __shared__ float sm[2][TPB / 32];
    #pragma unroll
    for (int o = 16; o; o >>= 1) {
        a0 += __shfl_down_sync(0xffffffffu, a0, o);
        a1 += __shfl_down_sync(0xffffffffu, a1, o);
    }
    int wid = threadIdx.x >> 5, lid = threadIdx.x & 31;
    if (lid == 0) { sm[0][wid] = a0; sm[1][wid] = a1; }
    __syncthreads();
    if (threadIdx.x < 32) {
        a0 = (lid < TPB / 32) ? sm[0][lid] : 0.f;
        a1 = (lid < TPB / 32) ? sm[1][lid] : 0.f;
        #pragma unroll
        for (int o = 16; o; o >>= 1) {
            a0 += __shfl_down_sync(0xffffffffu, a0, o);
            a1 += __shfl_down_sync(0xffffffffu, a1, o);
        }
        if (lid == 0) {
            atomicAdd(dst + s0 * 8, a0);
            if (s0 + 1 < NS && (s0 + 1) * H < r1) atomicAdd(dst + (s0 + 1) * 8, a1);
        }
    }
    __syncthreads();
}

// Iterate system-aligned segments of [q0,q1): calls f(s, i0, i1).
template<typename F>
__device__ __forceinline__ void for_segs(int q0, int q1, F f)
{
    int a = q0;
    while (a < q1) {
        int s = a >> 9;
        int send = q1 < ((s + 1) << 9) ? q1 : ((s + 1) << 9);
        f(s, a & 511, (a & 511) + (send - a));
        a = send;
    }
}

extern "C" __global__ void __launch_bounds__(TPB, 3)
cg_persistent(const float* __restrict__ Bin, const float* __restrict__ wc,
              const float* __restrict__ wr, float* __restrict__ x, int G)
{
    unsigned int gen = g_bar_phase;   // survives graph replays
    const int bi = blockIdx.x;
    const int r0 = (int)(((long long)bi * RTOT) / G);
    const int r1 = (int)(((long long)(bi + 1) * RTOT) / G);
    const int s0 = r0 >> 9;
    const int grp = threadIdx.x >> 7;
    const int j0 = (threadIdx.x & 127) << 2;
    const int lane = threadIdx.x & 31;
    const int q0 = r0 + (int)(((long long)(r1 - r0) * grp) / NGRP);
    const int q1 = r0 + (int)(((long long)(r1 - r0) * (grp + 1)) / NGRP);

    if (bi == 0) {
        for (int t = threadIdx.x; t < 3 * NS * 8; t += TPB) {
            (&g_pAp[0][0])[t] = 0.f;
            (&g_rr[0][0])[t] = 0.f;
        }
    }
    grid_barrier(G, gen);

    // Setup: x = B; r = B - A*B; rr0 -> slot 0
    {
        float a0 = 0.f, a1 = 0.f;
        for_segs(q0, q1, [&](int s, int i0, int i1) {
            int b = s / CH;
            float acc = 0.f;
            sweep_seg<0, false>(Bin + s * SYS, (const float*)0, 0.f,
                                wc + b * WCN, wr + b * WRN,
                                g_r + s * SYS, x + s * SYS, i0, i1, j0, lane, acc);
            if (s == s0) a0 += acc; else a1 += acc;
        });
        reduce2_atomic(a0, a1, s0, r1, g_rr[0]);
    }
    grid_barrier(G, gen);

    for (int it = 0; it < MAXIT; ++it) {
        const int cur = it % 3, prv = (it + 2) % 3, nxt = (it + 1) % 3;
        float* __restrict__ pnew = g_pbuf[it & 1];
        const float* __restrict__ pold = g_pbuf[(it + 1) & 1];

        // Pass 1: p = r + beta*p_old formed on load; store p; pAp dot (no Ap store)
        {
            float a0 = 0.f, a1 = 0.f;
            for_segs(q0, q1, [&](int s, int i0, int i1) {
                int b = s / CH;
                float acc = 0.f;
                if (it == 0) {
                    sweep_seg<1, false>(g_r + s * SYS, (const float*)0, 0.f,
                                        wc + b * WCN, wr + b * WRN,
                                        pnew + s * SYS, (float*)0, i0, i1, j0, lane, acc);
                } else {
                    float beta = nan0(g_rr[cur][s * 8] / g_rr[prv][s * 8]);
                    sweep_seg<1, true>(g_r + s * SYS, pold + s * SYS, beta,
                                       wc + b * WCN, wr + b * WRN,
                                       pnew + s * SYS, (float*)0, i0, i1, j0, lane, acc);
                }
                if (s == s0) a0 += acc; else a1 += acc;
            });
            reduce2_atomic(a0, a1, s0, r1, g_pAp[cur]);
            if (bi == 0) {
                for (int t = threadIdx.x; t < NS * 8; t += TPB) g_rr[nxt][t] = 0.f;
            }
        }
        grid_barrier(G, gen);

        // Pass 2: recompute Ap from p; r -= a*Ap; x += a*p; rr dot
        {
            float a0 = 0.f, a1 = 0.f;
            for_segs(q0, q1, [&](int s, int i0, int i1) {
                int b = s / CH;
                float alpha = nan0(g_rr[cur][s * 8] / g_pAp[cur][s * 8]);
                float acc = 0.f;
                sweep_seg<2, false>(pnew + s * SYS, (const float*)0, alpha,
                                    wc + b * WCN, wr + b * WRN,
                                    g_r + s * SYS, x + s * SYS, i0, i1, j0, lane, acc);
                if (s == s0) a0 += acc; else a1 += acc;
            });
            reduce2_atomic(a0, a1, s0, r1, g_rr[nxt]);
            if (bi == 0) {
                for (int t = threadIdx.x; t < NS * 8; t += TPB) g_pAp[nxt][t] = 0.f;
            }
        }
        grid_barrier(G, gen);

        // Convergence (uniform across blocks)
        __shared__ int s_done;
        if (threadIdx.x == 0) {
            float tot = 0.f;
            for (int s = 0; s < NS; ++s) tot += g_rr[nxt][s * 8];
            s_done = (tot < EPS_F) ? 1 : 0;
        }
        __syncthreads();
        if (s_done) break;
    }
}

extern "C" void kernel_launch(void* const* d_in, const int* in_sizes, int n_in,
                              void* d_out, int out_size)
{
    static int G = 0;
    if (G == 0) {
        int dev = 0;
        cudaGetDevice(&dev);
        int sms = 0;
        cudaDeviceGetAttribute(&sms, cudaDevAttrMultiProcessorCount, dev);
        int occ = 0;
        cudaOccupancyMaxActiveBlocksPerMultiprocessor(&occ, cg_persistent, TPB, 0);
        if (occ < 1) occ = 1;
        G = sms * occ;
        if (G > RTOT) G = RTOT;
    }
    cg_persistent<<<G, TPB>>>((const float*)d_in[0], (const float*)d_in[1],
                              (const float*)d_in[2], (float*)d_out, G);
}

// round 8
// speedup vs baseline: 1.1066x; 1.0046x over previous
#include <cuda_runtime.h>

#define H 512
#define W 512
#define CH 3
#define NB 16               // batches
#define NS 48               // 16 batches * 3 channels
#define SYS (H*W)
#define NTOT (NS*SYS)
#define RTOT (NS*H)         // 24576 rows
#define WCN (511*512)
#define WRN (512*511)
#define WPTOT (NB*SYS)      // padded row-weight elements
#define MAXIT 100
#define EPS_F 158.32966f    // (1e-6 * 16*3*512*512)^2
#define TPB 512
#define NGRP (TPB/128)      // 4 sweep groups per block

__device__ float g_r[NTOT];
__device__ float g_pbuf[2][NTOT];
__device__ float g_wrp[WPTOT];       // row weights, padded to stride 512 (col 511 = 0)
__device__ float g_pAp[3][NS*8];
__device__ float g_rr[3][NS*8];
__device__ unsigned int g_bar_arrive;
__device__ volatile unsigned int g_bar_phase;

__device__ __forceinline__ float4 ld4(const float* p) { return *reinterpret_cast<const float4*>(p); }
__device__ __forceinline__ void st4(float* p, float4 v) { *reinterpret_cast<float4*>(p) = v; }

__device__ __forceinline__ float nan0(float v) {
    if (isnan(v)) return 0.0f;
    if (isinf(v)) return v > 0.f ? 3.402823466e38f : -3.402823466e38f;
    return v;
}

__device__ __forceinline__ void grid_barrier(int G, unsigned int &gen) {
    __syncthreads();
    if (threadIdx.x == 0) {
        __threadfence();
        unsigned int t = atomicAdd(&g_bar_arrive, 1u);
        if (t == (unsigned int)(G - 1)) {
            g_bar_arrive = 0;
            __threadfence();
            g_bar_phase = gen + 1u;
        } else {
            while (g_bar_phase == gen) { __nanosleep(64); }
        }
        gen++;
        __threadfence();
    }
    __syncthreads();
}

// Register-rolling sweep over rows [i0,i1) of one system.
// z rolls in registers; column weights re-loaded per row (L1 hit for up-row).
// Row weights come from the PADDED stride-512 buffer (wrb) -> one aligned ld4.
// PASS 0 (setup): o1 <- z - y (=r), o2 <- z (=x), acc += |r|^2
// PASS 1:         o1 <- z (=p),                   acc += z . y  (p.Ap)
// PASS 2:         o1 -= coef*y (r), o2 += coef*z (x), acc += |r|^2
template<int PASS, bool COMBINE>
__device__ __forceinline__ void sweep_seg(
    const float* __restrict__ zsrc, const float* __restrict__ pb, float coef,
    const float* __restrict__ wcb, const float* __restrict__ wrb,
    float* __restrict__ o1, float* __restrict__ o2,
    int i0, int i1, int j0, int lane, float &acc)
{
    float4 zu = make_float4(0.f,0.f,0.f,0.f), zc, zd = make_float4(0.f,0.f,0.f,0.f);

    if (i0 > 0) {
        int e = (i0 - 1) * W + j0;
        zu = ld4(zsrc + e);
        if (COMBINE) {
            float4 q = ld4(pb + e);
            zu.x = fmaf(coef, q.x, zu.x); zu.y = fmaf(coef, q.y, zu.y);
            zu.z = fmaf(coef, q.z, zu.z); zu.w = fmaf(coef, q.w, zu.w);
        }
    }
    {
        int e = i0 * W + j0;
        zc = ld4(zsrc + e);
        if (COMBINE) {
            float4 q = ld4(pb + e);
            zc.x = fmaf(coef, q.x, zc.x); zc.y = fmaf(coef, q.y, zc.y);
            zc.z = fmaf(coef, q.z, zc.z); zc.w = fmaf(coef, q.w, zc.w);
        }
    }

    int gi = i0 * W + j0;
    for (int i = i0; i < i1; ++i, gi += W) {
        const bool dn = (i < H - 1);
        if (dn) {
            zd = ld4(zsrc + gi + W);
            if (COMBINE) {
                float4 q = ld4(pb + gi + W);
                zd.x = fmaf(coef, q.x, zd.x); zd.y = fmaf(coef, q.y, zd.y);
                zd.z = fmaf(coef, q.z, zd.z); zd.w = fmaf(coef, q.w, zd.w);
            }
        }

        // row weights: one aligned ld4 from the padded buffer (wv.w == 0 at j0=508)
        float4 wv = ld4(wrb + gi);
        float wl = __shfl_up_sync(0xffffffffu, wv.w, 1);
        float xl = __shfl_up_sync(0xffffffffu, zc.w, 1);
        float xr = __shfl_down_sync(0xffffffffu, zc.x, 1);
        if (lane == 0) {                    // warp-edge fixups (L1 hits)
            if (j0 > 0) {
                xl = zsrc[gi - 1];
                if (COMBINE) xl = fmaf(coef, pb[gi - 1], xl);
                wl = wrb[gi - 1];
            } else wl = 0.f;
        }
        if (lane == 31 && j0 + 4 < W) {
            xr = zsrc[gi + 4];
            if (COMBINE) xr = fmaf(coef, pb[gi + 4], xr);
        }

        float y0 = zc.x, y1 = zc.y, y2 = zc.z, y3 = zc.w;
        if (i > 0) {                         // up weights: re-load (L1 hit)
            float4 wu = ld4(wcb + (i - 1) * W + j0);
            y0 += wu.x * (zc.x - zu.x); y1 += wu.y * (zc.y - zu.y);
            y2 += wu.z * (zc.z - zu.z); y3 += wu.w * (zc.w - zu.w);
        }
        if (dn) {
            float4 wd = ld4(wcb + i * W + j0);
            y0 += wd.x * (zc.x - zd.x); y1 += wd.y * (zc.y - zd.y);
            y2 += wd.z * (zc.z - zd.z); y3 += wd.w * (zc.w - zd.w);
        }
        y0 += wv.x * (zc.x - zc.y);
        y1 += wv.x * (zc.y - zc.x) + wv.y * (zc.y - zc.z);
        y2 += wv.y * (zc.z - zc.y) + wv.z * (zc.z - zc.w);
        y3 += wv.z * (zc.w - zc.z);
        y0 += wl * (zc.x - xl);              // wl==0 at j0==0
        y3 += wv.w * (zc.w - xr);            // wv.w==0 at right edge (padded)

        if (PASS == 0) {
            float4 rn = make_float4(zc.x - y0, zc.y - y1, zc.z - y2, zc.w - y3);
            st4(o1 + gi, rn);
            st4(o2 + gi, zc);
            acc += rn.x * rn.x + rn.y * rn.y + rn.z * rn.z + rn.w * rn.w;
        } else if (PASS == 1) {
            st4(o1 + gi, zc);
            acc += zc.x * y0 + zc.y * y1 + zc.z * y2 + zc.w * y3;
        } else {
            float4 rv = ld4(o1 + gi);
            float4 xv = ld4(o2 + gi);
            rv.x -= coef * y0; rv.y -= coef * y1;
            rv.z -= coef * y2; rv.w -= coef * y3;
            xv.x = fmaf(coef, zc.x, xv.x); xv.y = fmaf(coef, zc.y, xv.y);
            xv.z = fmaf(coef, zc.z, xv.z); xv.w = fmaf(coef, zc.w, xv.w);
            st4(o1 + gi, rv);
            st4(o2 + gi, xv);
            acc += rv.x * rv.x + rv.y * rv.y + rv.z * rv.z + rv.w * rv.w;
        }
        zu = zc; zc = zd;
    }
}

// Block covers contiguous rows spanning at most 2 systems (s0, s0+1).
__device__ __forceinline__ void reduce2_atomic(float a0, float a1, int s0, int r1, float* dst)
{
    __shared__ float sm[2][TPB / 32];
    #pragma unroll
    for (int o = 16; o; o >>= 1) {
        a0 += __shfl_down_sync(0xffffffffu, a0, o);
        a1 += __shfl_down_sync(0xffffffffu, a1, o);
    }
    int wid = threadIdx.x >> 5, lid = threadIdx.x & 31;
    if (lid == 0) { sm[0][wid] = a0; sm[1][wid] = a1; }
    __syncthreads();
    if (threadIdx.x < 32) {
        a0 = (lid < TPB / 32) ? sm[0][lid] : 0.f;
        a1 = (lid < TPB / 32) ? sm[1][lid] : 0.f;
        #pragma unroll
        for (int o = 16; o; o >>= 1) {
            a0 += __shfl_down_sync(0xffffffffu, a0, o);
            a1 += __shfl_down_sync(0xffffffffu, a1, o);
        }
        if (lid == 0) {
            atomicAdd(dst + s0 * 8, a0);
            if (s0 + 1 < NS && (s0 + 1) * H < r1) atomicAdd(dst + (s0 + 1) * 8, a1);
        }
    }
    __syncthreads();
}

// Iterate system-aligned segments of [q0,q1): calls f(s, i0, i1).
template<typename F>
__device__ __forceinline__ void for_segs(int q0, int q1, F f)
{
    int a = q0;
    while (a < q1) {
        int s = a >> 9;
        int send = q1 < ((s + 1) << 9) ? q1 : ((s + 1) << 9);
        f(s, a & 511, (a & 511) + (send - a));
        a = send;
    }
}

extern "C" __global__ void __launch_bounds__(TPB, 3)
cg_persistent(const float* __restrict__ Bin, const float* __restrict__ wc,
              const float* __restrict__ wr, float* __restrict__ x, int G)
{
    unsigned int gen = g_bar_phase;   // survives graph replays
    const int bi = blockIdx.x;
    const int r0 = (int)(((long long)bi * RTOT) / G);
    const int r1 = (int)(((long long)(bi + 1) * RTOT) / G);
    const int s0 = r0 >> 9;
    const int grp = threadIdx.x >> 7;
    const int j0 = (threadIdx.x & 127) << 2;
    const int lane = threadIdx.x & 31;
    const int q0 = r0 + (int)(((long long)(r1 - r0) * grp) / NGRP);
    const int q1 = r0 + (int)(((long long)(r1 - r0) * (grp + 1)) / NGRP);

    // Phase Z: zero scalar slots + build padded row-weight buffer (all blocks)
    if (bi == 0) {
        for (int t = threadIdx.x; t < 3 * NS * 8; t += TPB) {
            (&g_pAp[0][0])[t] = 0.f;
            (&g_rr[0][0])[t] = 0.f;
        }
    }
    for (int t = bi * TPB + threadIdx.x; t < WPTOT; t += G * TPB) {
        int b = t >> 18;            // / SYS
        int rem = t & (SYS - 1);
        int i = rem >> 9, j = rem & 511;
        g_wrp[t] = (j < 511) ? wr[b * WRN + i * 511 + j] : 0.f;
    }
    grid_barrier(G, gen);

    // Setup: x = B; r = B - A*B; rr0 -> slot 0
    {
        float a0 = 0.f, a1 = 0.f;
        for_segs(q0, q1, [&](int s, int i0, int i1) {
            int b = s / CH;
            float acc = 0.f;
            sweep_seg<0, false>(Bin + s * SYS, (const float*)0, 0.f,
                                wc + b * WCN, g_wrp + b * SYS,
                                g_r + s * SYS, x + s * SYS, i0, i1, j0, lane, acc);
            if (s == s0) a0 += acc; else a1 += acc;
        });
        reduce2_atomic(a0, a1, s0, r1, g_rr[0]);
    }
    grid_barrier(G, gen);

    for (int it = 0; it < MAXIT; ++it) {
        const int cur = it % 3, prv = (it + 2) % 3, nxt = (it + 1) % 3;
        float* __restrict__ pnew = g_pbuf[it & 1];
        const float* __restrict__ pold = g_pbuf[(it + 1) & 1];

        // Pass 1: p = r + beta*p_old formed on load; store p; pAp dot (no Ap store)
        {
            float a0 = 0.f, a1 = 0.f;
            for_segs(q0, q1, [&](int s, int i0, int i1) {
                int b = s / CH;
                float acc = 0.f;
                if (it == 0) {
                    sweep_seg<1, false>(g_r + s * SYS, (const float*)0, 0.f,
                                        wc + b * WCN, g_wrp + b * SYS,
                                        pnew + s * SYS, (float*)0, i0, i1, j0, lane, acc);
                } else {
                    float beta = nan0(g_rr[cur][s * 8] / g_rr[prv][s * 8]);
                    sweep_seg<1, true>(g_r + s * SYS, pold + s * SYS, beta,
                                       wc + b * WCN, g_wrp + b * SYS,
                                       pnew + s * SYS, (float*)0, i0, i1, j0, lane, acc);
                }
                if (s == s0) a0 += acc; else a1 += acc;
            });
            reduce2_atomic(a0, a1, s0, r1, g_pAp[cur]);
            if (bi == 0) {
                for (int t = threadIdx.x; t < NS * 8; t += TPB) g_rr[nxt][t] = 0.f;
            }
        }
        grid_barrier(G, gen);

        // Pass 2: recompute Ap from p; r -= a*Ap; x += a*p; rr dot
        {
            float a0 = 0.f, a1 = 0.f;
            for_segs(q0, q1, [&](int s, int i0, int i1) {
                int b = s / CH;
                float alpha = nan0(g_rr[cur][s * 8] / g_pAp[cur][s * 8]);
                float acc = 0.f;
                sweep_seg<2, false>(pnew + s * SYS, (const float*)0, alpha,
                                    wc + b * WCN, g_wrp + b * SYS,
                                    g_r + s * SYS, x + s * SYS, i0, i1, j0, lane, acc);
                if (s == s0) a0 += acc; else a1 += acc;
            });
            reduce2_atomic(a0, a1, s0, r1, g_rr[nxt]);
            if (bi == 0) {
                for (int t = threadIdx.x; t < NS * 8; t += TPB) g_pAp[nxt][t] = 0.f;
            }
        }
        grid_barrier(G, gen);

        // Convergence (uniform across blocks)
        __shared__ int s_done;
        if (threadIdx.x == 0) {
            float tot = 0.f;
            for (int s = 0; s < NS; ++s) tot += g_rr[nxt][s * 8];
            s_done = (tot < EPS_F) ? 1 : 0;
        }
        __syncthreads();
        if (s_done) break;
    }
}

extern "C" void kernel_launch(void* const* d_in, const int* in_sizes, int n_in,
                              void* d_out, int out_size)
{
    static int G = 0;
    if (G == 0) {
        int dev = 0;
        cudaGetDevice(&dev);
        int sms = 0;
        cudaDeviceGetAttribute(&sms, cudaDevAttrMultiProcessorCount, dev);
        int occ = 0;
        cudaOccupancyMaxActiveBlocksPerMultiprocessor(&occ, cg_persistent, TPB, 0);
        if (occ < 1) occ = 1;
        G = sms * occ;
        if (G > RTOT) G = RTOT;
    }
    cg_persistent<<<G, TPB>>>((const float*)d_in[0], (const float*)d_in[1],
                              (const float*)d_in[2], (float*)d_out, G);
}